// round 1
// baseline (speedup 1.0000x reference)
#include <cuda_runtime.h>

typedef unsigned long long u64;

// ---------------- scratch (no allocations allowed) ----------------
__device__ float g_gi_f[64 * 1024 * 384];
__device__ float g_gi_b[64 * 1024 * 384];
__device__ float g_z0[64 * 1024 * 256];
__device__ float g_z1[64 * 1024 * 256];

// ---------------- f32x2 helpers ----------------
__device__ __forceinline__ u64 ffma2(u64 a, u64 b, u64 c) {
    u64 d;
    asm("fma.rn.f32x2 %0, %1, %2, %3;" : "=l"(d) : "l"(a), "l"(b), "l"(c));
    return d;
}
__device__ __forceinline__ u64 pack2(float lo, float hi) {
    u64 r;
    asm("mov.b64 %0, {%1, %2};" : "=l"(r) : "f"(lo), "f"(hi));
    return r;
}
__device__ __forceinline__ float2 unpack2(u64 v) {
    float2 f;
    asm("mov.b64 {%0, %1}, %2;" : "=f"(f.x), "=f"(f.y) : "l"(v));
    return f;
}

__device__ __forceinline__ float sigmoid_f(float x) {
    // accurate: ex2.approx based expf, rel err ~1e-6
    return __fdividef(1.0f, 1.0f + __expf(-x));
}
__device__ __forceinline__ float tanh_f(float x) {
    x = fminf(fmaxf(x, -15.0f), 15.0f);
    float e = __expf(-2.0f * x);
    return __fdividef(1.0f - e, 1.0f + e);
}

// ---------------- GEMM: C[M,384] = A[M,K] @ W[384,K]^T + bias ----------------
// BM=128, BN=64, BK=16, 256 threads, per-thread 8x4 via f32x2 (m-pairs packed).
// blockIdx.z selects fwd/bwd weight set (two independent GEMMs fused in one grid).
__global__ __launch_bounds__(256) void gemm2(
    const float* __restrict__ A,
    const float* __restrict__ Wf, const float* __restrict__ Wb,
    const float* __restrict__ bf, const float* __restrict__ bb,
    float* __restrict__ Cf, float* __restrict__ Cb,
    int K)
{
    const int N = 384;
    const float* W    = blockIdx.z ? Wb : Wf;
    const float* bias = blockIdx.z ? bb : bf;
    float*       C    = blockIdx.z ? Cb : Cf;

    const int mBase = blockIdx.y * 128;
    const int nBase = blockIdx.x * 64;
    const int tid = threadIdx.x;
    const int tx = tid & 15;
    const int ty = tid >> 4;

    __shared__ float As[16][130];   // As[k][m], padded -> conflict-free
    __shared__ u64   Wsd[16][65];   // duplicated pairs (w,w) per n

    u64 acc[4][4];
#pragma unroll
    for (int p = 0; p < 4; p++)
#pragma unroll
        for (int j = 0; j < 4; j++) acc[p][j] = 0ULL;

    const int la_m = tid >> 1;          // 0..127
    const int la_k = (tid & 1) * 8;     // 0 or 8
    const int lw_n = tid >> 2;          // 0..63
    const int lw_k = (tid & 3) * 4;     // 0,4,8,12

    const float* Ap = A + (long long)(mBase + la_m) * K + la_k;
    const float* Wp = W + (long long)(nBase + lw_n) * K + lw_k;

    for (int k0 = 0; k0 < K; k0 += 16) {
        float4 a0 = *(const float4*)(Ap + k0);
        float4 a1 = *(const float4*)(Ap + k0 + 4);
        float4 w0 = *(const float4*)(Wp + k0);
        __syncthreads();
        As[la_k + 0][la_m] = a0.x;
        As[la_k + 1][la_m] = a0.y;
        As[la_k + 2][la_m] = a0.z;
        As[la_k + 3][la_m] = a0.w;
        As[la_k + 4][la_m] = a1.x;
        As[la_k + 5][la_m] = a1.y;
        As[la_k + 6][la_m] = a1.z;
        As[la_k + 7][la_m] = a1.w;
        Wsd[lw_k + 0][lw_n] = pack2(w0.x, w0.x);
        Wsd[lw_k + 1][lw_n] = pack2(w0.y, w0.y);
        Wsd[lw_k + 2][lw_n] = pack2(w0.z, w0.z);
        Wsd[lw_k + 3][lw_n] = pack2(w0.w, w0.w);
        __syncthreads();
#pragma unroll
        for (int k = 0; k < 16; k++) {
            u64 av[4];
#pragma unroll
            for (int p = 0; p < 4; p++)
                av[p] = *(const u64*)&As[k][2 * (ty + 16 * p)];
            u64 bv[4];
#pragma unroll
            for (int j = 0; j < 4; j++)
                bv[j] = Wsd[k][tx + 16 * j];
#pragma unroll
            for (int p = 0; p < 4; p++)
#pragma unroll
                for (int j = 0; j < 4; j++)
                    acc[p][j] = ffma2(av[p], bv[j], acc[p][j]);
        }
    }

#pragma unroll
    for (int j = 0; j < 4; j++) {
        int n = nBase + tx + 16 * j;
        float bj = __ldg(&bias[n]);
#pragma unroll
        for (int p = 0; p < 4; p++) {
            float2 v = unpack2(acc[p][j]);
            int m = mBase + 2 * (ty + 16 * p);
            C[(long long)m * N + n]       = v.x + bj;
            C[(long long)(m + 1) * N + n] = v.y + bj;
        }
    }
}

// ---------------- GRU scan: 128 CTAs = 64 batch x 2 dirs; Whh in registers ----------------
__global__ __launch_bounds__(384, 1) void gru_scan(
    const float* __restrict__ gif, const float* __restrict__ gib,
    const float* __restrict__ whf, const float* __restrict__ bhf,
    const float* __restrict__ whb, const float* __restrict__ bhb,
    float* __restrict__ zout /* [64][1024][256] */)
{
    const int b   = blockIdx.x & 63;
    const int dir = blockIdx.x >> 6;
    const float* gi  = dir ? gib : gif;
    const float* whh = dir ? whb : whf;
    const float* bhh = dir ? bhb : bhf;
    const int j = threadIdx.x;   // 0..383  (rows: [0,128)=r, [128,256)=z, [256,384)=n)

    // thread j owns Whh row j as 64 packed f32x2 registers
    u64 w[64];
    {
        const u64* wp = (const u64*)(whh + j * 128);
#pragma unroll
        for (int k = 0; k < 64; k++) w[k] = wp[k];
    }
    const float bh = bhh[j];

    __shared__ __align__(16) float hsm[128];
    __shared__ float rsm[128];
    __shared__ float zsm[128];
    if (j < 128) hsm[j] = 0.0f;
    __syncthreads();

    const long long giBase = (long long)b * 1024 * 384;
    int tt = dir ? 1023 : 0;
    const int step = dir ? -1 : 1;
    float gcur = gi[giBase + (long long)tt * 384 + j];
    float* zrow = zout + (long long)b * 1024 * 256 + dir * 128;

    for (int t = 0; t < 1024; t++) {
        float gnext = 0.0f;
        if (t < 1023) gnext = gi[giBase + (long long)(tt + step) * 384 + j];

        // gh_j = Whh[j,:] . h  (64 FFMA2, h broadcast via LDS.128)
        u64 a0 = 0ULL, a1 = 0ULL;
        const ulonglong2* hp2 = (const ulonglong2*)hsm;
#pragma unroll
        for (int q = 0; q < 32; q++) {
            ulonglong2 u = hp2[q];
            a0 = ffma2(w[2 * q],     u.x, a0);
            a1 = ffma2(w[2 * q + 1], u.y, a1);
        }
        float2 f0 = unpack2(a0);
        float2 f1 = unpack2(a1);
        float gh = (f0.x + f0.y) + (f1.x + f1.y) + bh;

        if (j < 256) {
            float s = sigmoid_f(gcur + gh);
            if (j < 128) rsm[j] = s;
            else         zsm[j - 128] = s;
        }
        __syncthreads();
        if (j >= 256) {
            int i = j - 256;
            float n  = tanh_f(fmaf(rsm[i], gh, gcur));
            float zv = zsm[i];
            float hold = hsm[i];
            float hnew = fmaf(zv, hold - n, n);   // (1-z)n + z h
            hsm[i] = hnew;
            zrow[(long long)tt * 256 + i] = hnew;
        }
        __syncthreads();
        gcur = gnext;
        tt += step;
    }
}

// ---------------- attention pooling + heads ----------------
__global__ __launch_bounds__(256) void pool_heads(
    const float* __restrict__ z1,
    const float* __restrict__ attn_w, const float* __restrict__ attn_b,
    const float* __restrict__ motor_w, const float* __restrict__ motor_b,
    const float* __restrict__ state_w, const float* __restrict__ state_b,
    const int* __restrict__ motor_k,
    float* __restrict__ out)
{
    const int b = blockIdx.x;
    const int tid = threadIdx.x;
    const int lane = tid & 31;
    const int wrp = tid >> 5;

    __shared__ float aw[256];
    __shared__ float sc[1024];
    __shared__ float pl[256];
    __shared__ float red[40];

    aw[tid] = attn_w[tid];
    __syncthreads();

    const float* zb = z1 + (long long)b * 1024 * 256;

    // scores[t] = z[b,t,:].attn_w + attn_b   (warp per t)
    for (int it = 0; it < 128; it++) {
        int t = it * 8 + wrp;
        const float* zr = zb + (long long)t * 256;
        float p = 0.0f;
#pragma unroll
        for (int q = 0; q < 8; q++)
            p = fmaf(zr[lane + 32 * q], aw[lane + 32 * q], p);
#pragma unroll
        for (int o = 16; o; o >>= 1) p += __shfl_down_sync(0xffffffffu, p, o);
        if (lane == 0) sc[t] = p + attn_b[0];
    }
    __syncthreads();

    // softmax over t
    float mx = -1e30f;
    for (int t = tid; t < 1024; t += 256) mx = fmaxf(mx, sc[t]);
#pragma unroll
    for (int o = 16; o; o >>= 1) mx = fmaxf(mx, __shfl_down_sync(0xffffffffu, mx, o));
    if (lane == 0) red[wrp] = mx;
    __syncthreads();
    if (tid == 0) {
        float m = red[0];
        for (int i = 1; i < 8; i++) m = fmaxf(m, red[i]);
        red[32] = m;
    }
    __syncthreads();
    mx = red[32];
    float s = 0.0f;
    for (int t = tid; t < 1024; t += 256) {
        float e = __expf(sc[t] - mx);
        sc[t] = e;
        s += e;
    }
#pragma unroll
    for (int o = 16; o; o >>= 1) s += __shfl_down_sync(0xffffffffu, s, o);
    if (lane == 0) red[wrp] = s;
    __syncthreads();
    if (tid == 0) {
        float m = 0.0f;
        for (int i = 0; i < 8; i++) m += red[i];
        red[33] = __fdividef(1.0f, m);
    }
    __syncthreads();
    const float inv = red[33];

    // pooled[d] = sum_t a_t z[b,t,d]
    float accp = 0.0f;
    for (int t = 0; t < 1024; t++)
        accp = fmaf(sc[t], zb[(long long)t * 256 + tid], accp);
    pl[tid] = accp * inv;
    __syncthreads();

    // heads: warps 0..4 -> motor logits, warps 5..6 -> state logits
    if (wrp < 7) {
        const float* wv;
        float bias2;
        int k = motor_k[b];
        if (wrp < 5) {
            wv = motor_w + wrp * 256;
            bias2 = motor_b[wrp];
        } else {
            int c = wrp - 5;
            wv = state_w + (k * 2 + c) * 256;
            bias2 = state_b[k * 2 + c];
        }
        float p = 0.0f;
#pragma unroll
        for (int q = 0; q < 8; q++)
            p = fmaf(pl[lane + 32 * q], wv[lane + 32 * q], p);
#pragma unroll
        for (int o = 16; o; o >>= 1) p += __shfl_down_sync(0xffffffffu, p, o);
        if (lane == 0) {
            if (wrp < 5) out[b * 5 + wrp] = p + bias2;                 // logits_motor [64,5]
            else         out[320 + b * 2 + (wrp - 5)] = p + bias2;     // logits_state [64,2]
        }
    }
}

// ---------------- launcher ----------------
extern "C" void kernel_launch(void* const* d_in, const int* in_sizes, int n_in,
                              void* d_out, int out_size)
{
    const float* x        = (const float*)d_in[0];
    const int*   motor_k  = (const int*)d_in[1];
    const float* wih_l0f  = (const float*)d_in[2];
    const float* whh_l0f  = (const float*)d_in[3];
    const float* bih_l0f  = (const float*)d_in[4];
    const float* bhh_l0f  = (const float*)d_in[5];
    const float* wih_l0b  = (const float*)d_in[6];
    const float* whh_l0b  = (const float*)d_in[7];
    const float* bih_l0b  = (const float*)d_in[8];
    const float* bhh_l0b  = (const float*)d_in[9];
    const float* wih_l1f  = (const float*)d_in[10];
    const float* whh_l1f  = (const float*)d_in[11];
    const float* bih_l1f  = (const float*)d_in[12];
    const float* bhh_l1f  = (const float*)d_in[13];
    const float* wih_l1b  = (const float*)d_in[14];
    const float* whh_l1b  = (const float*)d_in[15];
    const float* bih_l1b  = (const float*)d_in[16];
    const float* bhh_l1b  = (const float*)d_in[17];
    const float* attn_w   = (const float*)d_in[18];
    const float* attn_b   = (const float*)d_in[19];
    const float* motor_w  = (const float*)d_in[20];
    const float* motor_b  = (const float*)d_in[21];
    const float* state_w  = (const float*)d_in[22];
    const float* state_b  = (const float*)d_in[23];

    float *gif, *gib, *z0, *z1;
    cudaGetSymbolAddress((void**)&gif, g_gi_f);
    cudaGetSymbolAddress((void**)&gib, g_gi_b);
    cudaGetSymbolAddress((void**)&z0, g_z0);
    cudaGetSymbolAddress((void**)&z1, g_z1);

    dim3 gb(384 / 64, 65536 / 128, 2);

    // layer 0
    gemm2<<<gb, 256>>>(x, wih_l0f, wih_l0b, bih_l0f, bih_l0b, gif, gib, 64);
    gru_scan<<<128, 384>>>(gif, gib, whh_l0f, bhh_l0f, whh_l0b, bhh_l0b, z0);
    // layer 1
    gemm2<<<gb, 256>>>(z0, wih_l1f, wih_l1b, bih_l1f, bih_l1b, gif, gib, 256);
    gru_scan<<<128, 384>>>(gif, gib, whh_l1f, bhh_l1f, whh_l1b, bhh_l1b, z1);
    // pooling + heads
    pool_heads<<<64, 256>>>(z1, attn_w, attn_b, motor_w, motor_b,
                            state_w, state_b, motor_k, (float*)d_out);
}

// round 2
// speedup vs baseline: 1.0519x; 1.0519x over previous
#include <cuda_runtime.h>

typedef unsigned long long u64;
typedef long long ll;

// ---------------- scratch (no allocations allowed) ----------------
__device__ float g_gi_f[64 * 1024 * 384];
__device__ float g_gi_b[64 * 1024 * 384];
__device__ float g_z0[64 * 1024 * 256];
__device__ float g_z1[64 * 1024 * 256];

// ---------------- f32x2 helpers ----------------
__device__ __forceinline__ u64 ffma2(u64 a, u64 b, u64 c) {
    u64 d;
    asm("fma.rn.f32x2 %0, %1, %2, %3;" : "=l"(d) : "l"(a), "l"(b), "l"(c));
    return d;
}
__device__ __forceinline__ u64 addf2(u64 a, u64 b) {
    u64 d;
    asm("add.rn.f32x2 %0, %1, %2;" : "=l"(d) : "l"(a), "l"(b));
    return d;
}
__device__ __forceinline__ u64 pack2(float lo, float hi) {
    u64 r;
    asm("mov.b64 %0, {%1, %2};" : "=l"(r) : "f"(lo), "f"(hi));
    return r;
}
__device__ __forceinline__ float2 unpack2(u64 v) {
    float2 f;
    asm("mov.b64 {%0, %1}, %2;" : "=f"(f.x), "=f"(f.y) : "l"(v));
    return f;
}

__device__ __forceinline__ float tanh_mufu(float x) {
    float y;
    asm("tanh.approx.f32 %0, %1;" : "=f"(y) : "f"(x));
    return y;
}
__device__ __forceinline__ float sig_mufu(float x) {
    // sigma(x) = 0.5 * tanh(x/2) + 0.5
    return fmaf(0.5f, tanh_mufu(0.5f * x), 0.5f);
}
__device__ __forceinline__ float sigmoid_exact(float x) {
    return __fdividef(1.0f, 1.0f + __expf(-x));
}

// ---------------- GEMM: C[M,384] = A[M,K] @ W[384,K]^T + bias ----------------
// BM=128, BN=128, BK=16, 256 threads, per-thread 8x8 via f32x2 (n-pairs packed).
// A duplicated into (a,a) pairs in registers (MOV), W transposed in smem so
// n-pairs load as native u64. blockIdx.z selects fwd/bwd weight set.
__global__ __launch_bounds__(256, 2) void gemm2(
    const float* __restrict__ A,
    const float* __restrict__ Wf, const float* __restrict__ Wb,
    const float* __restrict__ bf, const float* __restrict__ bb,
    float* __restrict__ Cf, float* __restrict__ Cb,
    int K)
{
    const int N = 384;
    const float* W    = blockIdx.z ? Wb : Wf;
    const float* bias = blockIdx.z ? bb : bf;
    float*       C    = blockIdx.z ? Cb : Cf;

    const int mBase = blockIdx.y * 128;
    const int nBase = blockIdx.x * 128;
    const int tid = threadIdx.x;
    const int tx = tid & 15;        // n octet
    const int ty = tid >> 4;        // m octet
    const int m0 = ty * 8;
    const int n0 = tx * 8;

    __shared__ float As[16][132];   // As[k][m]
    __shared__ float Wt[16][132];   // Wt[k][n]  (transposed W tile)

    u64 acc[8][4];
#pragma unroll
    for (int mi = 0; mi < 8; mi++)
#pragma unroll
        for (int nj = 0; nj < 4; nj++) acc[mi][nj] = 0ULL;

    const int la_m = tid >> 1;          // 0..127 (also n index for W tile)
    const int la_k = (tid & 1) * 8;     // 0 or 8

    const float* Ap = A + (ll)(mBase + la_m) * K + la_k;
    const float* Wp = W + (ll)(nBase + la_m) * K + la_k;

    for (int k0 = 0; k0 < K; k0 += 16) {
        float4 a0 = *(const float4*)(Ap + k0);
        float4 a1 = *(const float4*)(Ap + k0 + 4);
        float4 w0 = *(const float4*)(Wp + k0);
        float4 w1 = *(const float4*)(Wp + k0 + 4);
        __syncthreads();
        As[la_k + 0][la_m] = a0.x;
        As[la_k + 1][la_m] = a0.y;
        As[la_k + 2][la_m] = a0.z;
        As[la_k + 3][la_m] = a0.w;
        As[la_k + 4][la_m] = a1.x;
        As[la_k + 5][la_m] = a1.y;
        As[la_k + 6][la_m] = a1.z;
        As[la_k + 7][la_m] = a1.w;
        Wt[la_k + 0][la_m] = w0.x;
        Wt[la_k + 1][la_m] = w0.y;
        Wt[la_k + 2][la_m] = w0.z;
        Wt[la_k + 3][la_m] = w0.w;
        Wt[la_k + 4][la_m] = w1.x;
        Wt[la_k + 5][la_m] = w1.y;
        Wt[la_k + 6][la_m] = w1.z;
        Wt[la_k + 7][la_m] = w1.w;
        __syncthreads();
#pragma unroll
        for (int k = 0; k < 16; k++) {
            float4 aL = *(const float4*)&As[k][m0];
            float4 aH = *(const float4*)&As[k][m0 + 4];
            u64 am[8];
            am[0] = pack2(aL.x, aL.x);
            am[1] = pack2(aL.y, aL.y);
            am[2] = pack2(aL.z, aL.z);
            am[3] = pack2(aL.w, aL.w);
            am[4] = pack2(aH.x, aH.x);
            am[5] = pack2(aH.y, aH.y);
            am[6] = pack2(aH.z, aH.z);
            am[7] = pack2(aH.w, aH.w);
            ulonglong2 b01 = *(const ulonglong2*)&Wt[k][n0];
            ulonglong2 b23 = *(const ulonglong2*)&Wt[k][n0 + 4];
            u64 bn[4] = { b01.x, b01.y, b23.x, b23.y };
#pragma unroll
            for (int mi = 0; mi < 8; mi++)
#pragma unroll
                for (int nj = 0; nj < 4; nj++)
                    acc[mi][nj] = ffma2(am[mi], bn[nj], acc[mi][nj]);
        }
    }

    // epilogue: + bias, store
    ulonglong2 bv01 = *(const ulonglong2*)(bias + nBase + n0);
    ulonglong2 bv23 = *(const ulonglong2*)(bias + nBase + n0 + 4);
#pragma unroll
    for (int mi = 0; mi < 8; mi++) {
        float* row = C + (ll)(mBase + m0 + mi) * N + nBase + n0;
        ulonglong2 v0, v1;
        v0.x = addf2(acc[mi][0], bv01.x);
        v0.y = addf2(acc[mi][1], bv01.y);
        v1.x = addf2(acc[mi][2], bv23.x);
        v1.y = addf2(acc[mi][3], bv23.y);
        *(ulonglong2*)(row)     = v0;
        *(ulonglong2*)(row + 4) = v1;
    }
}

// ---------------- GRU scan: 128 CTAs = 64 batch x 2 dirs; Whh in registers ----------------
__global__ __launch_bounds__(384, 1) void gru_scan(
    const float* __restrict__ gif, const float* __restrict__ gib,
    const float* __restrict__ whf, const float* __restrict__ bhf,
    const float* __restrict__ whb, const float* __restrict__ bhb,
    float* __restrict__ zout /* [64][1024][256] */)
{
    const int b   = blockIdx.x & 63;
    const int dir = blockIdx.x >> 6;
    const float* gi  = dir ? gib : gif;
    const float* whh = dir ? whb : whf;
    const float* bhh = dir ? bhb : bhf;
    const int j = threadIdx.x;   // rows: [0,128)=r, [128,256)=z, [256,384)=n

    // thread j owns Whh row j as 64 packed f32x2 registers
    u64 w[64];
    {
        const u64* wp = (const u64*)(whh + j * 128);
#pragma unroll
        for (int k = 0; k < 64; k++) w[k] = wp[k];
    }
    const float bh = bhh[j];

    __shared__ __align__(16) float hsm[128];
    __shared__ float rsm[128];
    __shared__ float zsm[128];
    if (j < 128) hsm[j] = 0.0f;
    __syncthreads();

    const int step = dir ? -1 : 1;
    int tt = dir ? 1023 : 0;
    const float* gip = gi + (ll)b * 1024 * 384 + j;
    float gcur = gip[(ll)tt * 384];
    float* zrow = zout + (ll)b * 1024 * 256 + dir * 128;

    for (int t = 0; t < 1024; t++) {
        // unconditional 1-step-ahead prefetch (wrap index; last value unused)
        int tn = (tt + step) & 1023;
        float gnext = gip[(ll)tn * 384];

        // gh_j = Whh[j,:] . h  (64 FFMA2, 4 chains of depth 16; h broadcast LDS.128)
        u64 a0 = 0ULL, a1 = 0ULL, a2 = 0ULL, a3 = 0ULL;
        const ulonglong2* hp2 = (const ulonglong2*)hsm;
#pragma unroll
        for (int q = 0; q < 16; q++) {
            ulonglong2 u0 = hp2[2 * q];
            ulonglong2 u1 = hp2[2 * q + 1];
            a0 = ffma2(w[4 * q + 0], u0.x, a0);
            a1 = ffma2(w[4 * q + 1], u0.y, a1);
            a2 = ffma2(w[4 * q + 2], u1.x, a2);
            a3 = ffma2(w[4 * q + 3], u1.y, a3);
        }
        float2 f0 = unpack2(a0), f1 = unpack2(a1);
        float2 f2 = unpack2(a2), f3 = unpack2(a3);
        float gh = ((f0.x + f0.y) + (f1.x + f1.y)) +
                   ((f2.x + f2.y) + (f3.x + f3.y)) + bh;

        float hold = 0.0f;
        if (j >= 256) hold = hsm[j - 256];     // preload before barrier (h stable)
        if (j < 128) {
            rsm[j] = sig_mufu(gcur + gh);      // fast path: r on critical chain
        } else if (j < 256) {
            zsm[j - 128] = sigmoid_exact(gcur + gh);  // accurate z (memory gate)
        }
        __syncthreads();
        if (j >= 256) {
            int i = j - 256;
            float n = tanh_mufu(fmaf(rsm[i], gh, gcur));
            float hnew = fmaf(zsm[i], hold - n, n);   // (1-z)n + z h
            hsm[i] = hnew;
            zrow[(ll)tt * 256 + i] = hnew;
        }
        __syncthreads();
        gcur = gnext;
        tt += step;
    }
}

// ---------------- attention pooling + heads ----------------
__global__ __launch_bounds__(256) void pool_heads(
    const float* __restrict__ z1,
    const float* __restrict__ attn_w, const float* __restrict__ attn_b,
    const float* __restrict__ motor_w, const float* __restrict__ motor_b,
    const float* __restrict__ state_w, const float* __restrict__ state_b,
    const int* __restrict__ motor_k,
    float* __restrict__ out)
{
    const int b = blockIdx.x;
    const int tid = threadIdx.x;
    const int lane = tid & 31;
    const int wrp = tid >> 5;

    __shared__ float aw[256];
    __shared__ float sc[1024];
    __shared__ float pl[256];
    __shared__ float red[40];

    aw[tid] = attn_w[tid];
    __syncthreads();

    const float* zb = z1 + (ll)b * 1024 * 256;

    for (int it = 0; it < 128; it++) {
        int t = it * 8 + wrp;
        const float* zr = zb + (ll)t * 256;
        float p = 0.0f;
#pragma unroll
        for (int q = 0; q < 8; q++)
            p = fmaf(zr[lane + 32 * q], aw[lane + 32 * q], p);
#pragma unroll
        for (int o = 16; o; o >>= 1) p += __shfl_down_sync(0xffffffffu, p, o);
        if (lane == 0) sc[t] = p + attn_b[0];
    }
    __syncthreads();

    float mx = -1e30f;
    for (int t = tid; t < 1024; t += 256) mx = fmaxf(mx, sc[t]);
#pragma unroll
    for (int o = 16; o; o >>= 1) mx = fmaxf(mx, __shfl_down_sync(0xffffffffu, mx, o));
    if (lane == 0) red[wrp] = mx;
    __syncthreads();
    if (tid == 0) {
        float m = red[0];
        for (int i = 1; i < 8; i++) m = fmaxf(m, red[i]);
        red[32] = m;
    }
    __syncthreads();
    mx = red[32];
    float s = 0.0f;
    for (int t = tid; t < 1024; t += 256) {
        float e = __expf(sc[t] - mx);
        sc[t] = e;
        s += e;
    }
#pragma unroll
    for (int o = 16; o; o >>= 1) s += __shfl_down_sync(0xffffffffu, s, o);
    if (lane == 0) red[wrp] = s;
    __syncthreads();
    if (tid == 0) {
        float m = 0.0f;
        for (int i = 0; i < 8; i++) m += red[i];
        red[33] = __fdividef(1.0f, m);
    }
    __syncthreads();
    const float inv = red[33];

    float accp = 0.0f;
    for (int t = 0; t < 1024; t++)
        accp = fmaf(sc[t], zb[(ll)t * 256 + tid], accp);
    pl[tid] = accp * inv;
    __syncthreads();

    if (wrp < 7) {
        const float* wv;
        float bias2;
        int k = motor_k[b];
        if (wrp < 5) {
            wv = motor_w + wrp * 256;
            bias2 = motor_b[wrp];
        } else {
            int c = wrp - 5;
            wv = state_w + (k * 2 + c) * 256;
            bias2 = state_b[k * 2 + c];
        }
        float p = 0.0f;
#pragma unroll
        for (int q = 0; q < 8; q++)
            p = fmaf(pl[lane + 32 * q], wv[lane + 32 * q], p);
#pragma unroll
        for (int o = 16; o; o >>= 1) p += __shfl_down_sync(0xffffffffu, p, o);
        if (lane == 0) {
            if (wrp < 5) out[b * 5 + wrp] = p + bias2;
            else         out[320 + b * 2 + (wrp - 5)] = p + bias2;
        }
    }
}

// ---------------- launcher ----------------
extern "C" void kernel_launch(void* const* d_in, const int* in_sizes, int n_in,
                              void* d_out, int out_size)
{
    const float* x        = (const float*)d_in[0];
    const int*   motor_k  = (const int*)d_in[1];
    const float* wih_l0f  = (const float*)d_in[2];
    const float* whh_l0f  = (const float*)d_in[3];
    const float* bih_l0f  = (const float*)d_in[4];
    const float* bhh_l0f  = (const float*)d_in[5];
    const float* wih_l0b  = (const float*)d_in[6];
    const float* whh_l0b  = (const float*)d_in[7];
    const float* bih_l0b  = (const float*)d_in[8];
    const float* bhh_l0b  = (const float*)d_in[9];
    const float* wih_l1f  = (const float*)d_in[10];
    const float* whh_l1f  = (const float*)d_in[11];
    const float* bih_l1f  = (const float*)d_in[12];
    const float* bhh_l1f  = (const float*)d_in[13];
    const float* wih_l1b  = (const float*)d_in[14];
    const float* whh_l1b  = (const float*)d_in[15];
    const float* bih_l1b  = (const float*)d_in[16];
    const float* bhh_l1b  = (const float*)d_in[17];
    const float* attn_w   = (const float*)d_in[18];
    const float* attn_b   = (const float*)d_in[19];
    const float* motor_w  = (const float*)d_in[20];
    const float* motor_b  = (const float*)d_in[21];
    const float* state_w  = (const float*)d_in[22];
    const float* state_b  = (const float*)d_in[23];

    float *gif, *gib, *z0, *z1;
    cudaGetSymbolAddress((void**)&gif, g_gi_f);
    cudaGetSymbolAddress((void**)&gib, g_gi_b);
    cudaGetSymbolAddress((void**)&z0, g_z0);
    cudaGetSymbolAddress((void**)&z1, g_z1);

    dim3 gb(3, 512, 2);   // N/128, M/128, dirs

    // layer 0
    gemm2<<<gb, 256>>>(x, wih_l0f, wih_l0b, bih_l0f, bih_l0b, gif, gib, 64);
    gru_scan<<<128, 384>>>(gif, gib, whh_l0f, bhh_l0f, whh_l0b, bhh_l0b, z0);
    // layer 1
    gemm2<<<gb, 256>>>(z0, wih_l1f, wih_l1b, bih_l1f, bih_l1b, gif, gib, 256);
    gru_scan<<<128, 384>>>(gif, gib, whh_l1f, bhh_l1f, whh_l1b, bhh_l1b, z1);
    // pooling + heads
    pool_heads<<<64, 256>>>(z1, attn_w, attn_b, motor_w, motor_b,
                            state_w, state_b, motor_k, (float*)d_out);
}